// round 2
// baseline (speedup 1.0000x reference)
#include <cuda_runtime.h>

#define BATCH 2
#define SEQ 2048
#define DMODEL 2048
#define NHEAD 16
#define HDIM 128
#define MTOT (BATCH*SEQ)   // 4096

// Scratch buffers (device globals: allocation-free)
__device__ float g_q[MTOT*DMODEL];
__device__ float g_k[MTOT*DMODEL];
__device__ float g_v[MTOT*DMODEL];
__device__ float g_ctx[MTOT*DMODEL];

// ---------------------------------------------------------------------------
// C[M,N] = A[M,K] @ B[N,K]^T (+ bias[N])   (torch Linear semantics)
// BM=BN=128, BK=16, 256 threads, 8x8 micro-tile, double-buffered smem.
// ---------------------------------------------------------------------------
__global__ __launch_bounds__(256, 2)
void gemm_nt(const float* __restrict__ A, const float* __restrict__ B,
             float* __restrict__ C, const float* __restrict__ bias,
             int M, int N, int K)
{
    constexpr int BM = 128, BN = 128, BK = 16;
    __shared__ float As[2][BK][BM];
    __shared__ float Bs[2][BK][BN];

    const int tid = threadIdx.x;
    const int ty = tid >> 4;      // 0..15 -> row group
    const int tx = tid & 15;      // 0..15 -> col group
    const int m0 = blockIdx.y * BM;
    const int n0 = blockIdx.x * BN;

    float acc[8][8];
#pragma unroll
    for (int i = 0; i < 8; i++)
#pragma unroll
        for (int j = 0; j < 8; j++) acc[i][j] = 0.f;

    const float* Abase = A + (long)m0 * K;
    const float* Bbase = B + (long)n0 * K;

    // preload stage 0: each thread loads 2 float4 from A and 2 from B
#pragma unroll
    for (int i = 0; i < 2; i++) {
        int id  = tid + 256 * i;
        int row = id >> 2;
        int kc  = (id & 3) * 4;
        float4 va = *(const float4*)(Abase + (long)row * K + kc);
        float4 vb = *(const float4*)(Bbase + (long)row * K + kc);
        As[0][kc+0][row] = va.x; As[0][kc+1][row] = va.y;
        As[0][kc+2][row] = va.z; As[0][kc+3][row] = va.w;
        Bs[0][kc+0][row] = vb.x; Bs[0][kc+1][row] = vb.y;
        Bs[0][kc+2][row] = vb.z; Bs[0][kc+3][row] = vb.w;
    }
    __syncthreads();

    const int nk = K / BK;
    for (int kt = 0; kt < nk; kt++) {
        const int cur = kt & 1;
        float4 pa[2], pb[2];
        if (kt + 1 < nk) {
#pragma unroll
            for (int i = 0; i < 2; i++) {
                int id  = tid + 256 * i;
                int row = id >> 2;
                int kc  = (id & 3) * 4;
                pa[i] = *(const float4*)(Abase + (long)row * K + (kt+1)*BK + kc);
                pb[i] = *(const float4*)(Bbase + (long)row * K + (kt+1)*BK + kc);
            }
        }
#pragma unroll
        for (int k = 0; k < BK; k++) {
            float4 a0 = *(const float4*)&As[cur][k][ty*8];
            float4 a1 = *(const float4*)&As[cur][k][ty*8 + 4];
            float4 b0 = *(const float4*)&Bs[cur][k][tx*8];
            float4 b1 = *(const float4*)&Bs[cur][k][tx*8 + 4];
            float av[8] = {a0.x,a0.y,a0.z,a0.w,a1.x,a1.y,a1.z,a1.w};
            float bv[8] = {b0.x,b0.y,b0.z,b0.w,b1.x,b1.y,b1.z,b1.w};
#pragma unroll
            for (int i = 0; i < 8; i++)
#pragma unroll
                for (int j = 0; j < 8; j++) acc[i][j] += av[i]*bv[j];
        }
        if (kt + 1 < nk) {
            const int nxt = cur ^ 1;
#pragma unroll
            for (int i = 0; i < 2; i++) {
                int id  = tid + 256 * i;
                int row = id >> 2;
                int kc  = (id & 3) * 4;
                As[nxt][kc+0][row] = pa[i].x; As[nxt][kc+1][row] = pa[i].y;
                As[nxt][kc+2][row] = pa[i].z; As[nxt][kc+3][row] = pa[i].w;
                Bs[nxt][kc+0][row] = pb[i].x; Bs[nxt][kc+1][row] = pb[i].y;
                Bs[nxt][kc+2][row] = pb[i].z; Bs[nxt][kc+3][row] = pb[i].w;
            }
        }
        __syncthreads();
    }

    // epilogue
    float badd[8];
#pragma unroll
    for (int j = 0; j < 8; j++)
        badd[j] = bias ? bias[n0 + tx*8 + j] : 0.f;
#pragma unroll
    for (int i = 0; i < 8; i++) {
        int row = m0 + ty*8 + i;
        float* Crow = C + (long)row * N + n0 + tx*8;
        float4 r0 = make_float4(acc[i][0]+badd[0], acc[i][1]+badd[1],
                                acc[i][2]+badd[2], acc[i][3]+badd[3]);
        float4 r1 = make_float4(acc[i][4]+badd[4], acc[i][5]+badd[5],
                                acc[i][6]+badd[6], acc[i][7]+badd[7]);
        *(float4*)(Crow)     = r0;
        *(float4*)(Crow + 4) = r1;
    }
}

// ---------------------------------------------------------------------------
// Causal flash attention, fp32. One CTA = 64 query rows of one (b, h).
// Q,K,V,O laid out [b*S + s][h*HD + d] (i.e. the projection output layout).
// smem: Qt[128][64] (k-major), Kt[128][64] (k-major), Vs[64][128], Ps[64][64]
// ---------------------------------------------------------------------------
__global__ __launch_bounds__(256)
void attn_kernel(const float* __restrict__ Q, const float* __restrict__ K,
                 const float* __restrict__ V, float* __restrict__ O)
{
    extern __shared__ float sm[];
    float* Qt = sm;                 // [128][64]
    float* Kt = Qt + 128*64;        // [128][64]
    float* Vs = Kt + 128*64;        // [64][128]
    float* Ps = Vs + 64*128;        // [64][64]  (row-major: [qrow][kcol])

    const int tid = threadIdx.x;
    const int ty  = tid >> 4;       // 0..15  query-row group (4 rows)
    const int tx  = tid & 15;       // 0..15  kv-col group (4 cols) / out-col group (8)
    const int qt  = blockIdx.x;     // query tile, 0..31
    const int h   = blockIdx.y;
    const int b   = blockIdx.z;
    const int q0  = qt * 64;

    const float* Qg = Q + ((long)(b*SEQ + q0)) * DMODEL + h*HDIM;

    // load Q tile, transposed to k-major
#pragma unroll
    for (int i = 0; i < 8; i++) {
        int id = tid + 256 * i;
        int r  = id >> 5;           // 0..63
        int kc = (id & 31) * 4;     // 0..124
        float4 v4 = *(const float4*)(Qg + (long)r * DMODEL + kc);
        Qt[(kc+0)*64 + r] = v4.x;
        Qt[(kc+1)*64 + r] = v4.y;
        Qt[(kc+2)*64 + r] = v4.z;
        Qt[(kc+3)*64 + r] = v4.w;
    }

    float m[4], l[4], o[4][8];
#pragma unroll
    for (int i = 0; i < 4; i++) {
        m[i] = -1e30f; l[i] = 0.f;
#pragma unroll
        for (int c = 0; c < 8; c++) o[i][c] = 0.f;
    }

    const float sm_scale = 0.08838834764831845f;  // 1/sqrt(128)

    __syncthreads();

    for (int kt = 0; kt <= qt; kt++) {
        const int k0 = kt * 64;
        const float* Kg = K + ((long)(b*SEQ + k0)) * DMODEL + h*HDIM;
        const float* Vg = V + ((long)(b*SEQ + k0)) * DMODEL + h*HDIM;
#pragma unroll
        for (int i = 0; i < 8; i++) {
            int id = tid + 256 * i;
            int r  = id >> 5;
            int kc = (id & 31) * 4;
            float4 v4 = *(const float4*)(Kg + (long)r * DMODEL + kc);
            Kt[(kc+0)*64 + r] = v4.x;
            Kt[(kc+1)*64 + r] = v4.y;
            Kt[(kc+2)*64 + r] = v4.z;
            Kt[(kc+3)*64 + r] = v4.w;
            float4 w4 = *(const float4*)(Vg + (long)r * DMODEL + kc);
            *(float4*)&Vs[r*128 + kc] = w4;
        }
        __syncthreads();

        // scores S = Q @ K^T  (4x4 per thread)
        float s[4][4];
#pragma unroll
        for (int i = 0; i < 4; i++)
#pragma unroll
            for (int j = 0; j < 4; j++) s[i][j] = 0.f;

        for (int kk = 0; kk < 128; kk++) {
            float4 a  = *(const float4*)&Qt[kk*64 + ty*4];
            float4 bq = *(const float4*)&Kt[kk*64 + tx*4];
            float av[4] = {a.x, a.y, a.z, a.w};
            float bv[4] = {bq.x, bq.y, bq.z, bq.w};
#pragma unroll
            for (int i = 0; i < 4; i++)
#pragma unroll
                for (int j = 0; j < 4; j++) s[i][j] += av[i]*bv[j];
        }

        // scale + causal mask
#pragma unroll
        for (int i = 0; i < 4; i++) {
            int qg = q0 + ty*4 + i;
#pragma unroll
            for (int j = 0; j < 4; j++) {
                int kg = k0 + tx*4 + j;
                s[i][j] = (kg <= qg) ? s[i][j]*sm_scale : -1e30f;
            }
        }

        // online softmax per row (reduce across the 16 tx lanes of a half-warp)
#pragma unroll
        for (int i = 0; i < 4; i++) {
            float mx = fmaxf(fmaxf(s[i][0], s[i][1]), fmaxf(s[i][2], s[i][3]));
#pragma unroll
            for (int off = 8; off > 0; off >>= 1)
                mx = fmaxf(mx, __shfl_xor_sync(0xffffffffu, mx, off));
            float mnew = fmaxf(m[i], mx);
            float corr = __expf(m[i] - mnew);
            float p[4], rs = 0.f;
#pragma unroll
            for (int j = 0; j < 4; j++) { p[j] = __expf(s[i][j] - mnew); rs += p[j]; }
#pragma unroll
            for (int off = 8; off > 0; off >>= 1)
                rs += __shfl_xor_sync(0xffffffffu, rs, off);
            l[i] = l[i]*corr + rs;
            m[i] = mnew;
#pragma unroll
            for (int c = 0; c < 8; c++) o[i][c] *= corr;
            *(float4*)&Ps[(ty*4 + i)*64 + tx*4] = make_float4(p[0], p[1], p[2], p[3]);
        }
        __syncthreads();

        // O += P @ V   (4 rows x 8 cols per thread)
#pragma unroll 4
        for (int j = 0; j < 64; j++) {
            float pr[4];
#pragma unroll
            for (int i = 0; i < 4; i++) pr[i] = Ps[(ty*4 + i)*64 + j];
            float4 v0 = *(const float4*)&Vs[j*128 + tx*8];
            float4 v1 = *(const float4*)&Vs[j*128 + tx*8 + 4];
            float vv[8] = {v0.x,v0.y,v0.z,v0.w,v1.x,v1.y,v1.z,v1.w};
#pragma unroll
            for (int i = 0; i < 4; i++)
#pragma unroll
                for (int c = 0; c < 8; c++) o[i][c] += pr[i]*vv[c];
        }
        __syncthreads();
    }

    // write out (normalized)
    float* Og = O + ((long)(b*SEQ + q0)) * DMODEL + h*HDIM;
#pragma unroll
    for (int i = 0; i < 4; i++) {
        float inv = 1.f / l[i];
        float4 r0 = make_float4(o[i][0]*inv, o[i][1]*inv, o[i][2]*inv, o[i][3]*inv);
        float4 r1 = make_float4(o[i][4]*inv, o[i][5]*inv, o[i][6]*inv, o[i][7]*inv);
        *(float4*)(Og + (long)(ty*4 + i)*DMODEL + tx*8)     = r0;
        *(float4*)(Og + (long)(ty*4 + i)*DMODEL + tx*8 + 4) = r1;
    }
}

// ---------------------------------------------------------------------------
// Host launcher
// ---------------------------------------------------------------------------
extern "C" void kernel_launch(void* const* d_in, const int* in_sizes, int n_in,
                              void* d_out, int out_size)
{
    const float* x  = (const float*)d_in[0];
    const float* wq = (const float*)d_in[1];
    const float* wk = (const float*)d_in[2];
    const float* wv = (const float*)d_in[3];
    const float* wo = (const float*)d_in[4];
    const float* bo = (const float*)d_in[5];
    float* out = (float*)d_out;

    float *q, *k, *v, *ctx;
    cudaGetSymbolAddress((void**)&q,   g_q);
    cudaGetSymbolAddress((void**)&k,   g_k);
    cudaGetSymbolAddress((void**)&v,   g_v);
    cudaGetSymbolAddress((void**)&ctx, g_ctx);

    const int SMEM_BYTES = (128*64 + 128*64 + 64*128 + 64*64) * (int)sizeof(float); // 114688
    cudaFuncSetAttribute(attn_kernel, cudaFuncAttributeMaxDynamicSharedMemorySize, SMEM_BYTES);

    dim3 gg(DMODEL/128, MTOT/128);   // 16 x 32 = 512 CTAs per GEMM
    gemm_nt<<<gg, 256>>>(x,   wq, q,   nullptr, MTOT, DMODEL, DMODEL);
    gemm_nt<<<gg, 256>>>(x,   wk, k,   nullptr, MTOT, DMODEL, DMODEL);
    gemm_nt<<<gg, 256>>>(x,   wv, v,   nullptr, MTOT, DMODEL, DMODEL);

    attn_kernel<<<dim3(SEQ/64, NHEAD, BATCH), 256, SMEM_BYTES>>>(q, k, v, ctx);

    gemm_nt<<<gg, 256>>>(ctx, wo, out, bo,      MTOT, DMODEL, DMODEL);
}

// round 3
// speedup vs baseline: 1.7572x; 1.7572x over previous
#include <cuda_runtime.h>
#include <cuda_bf16.h>
#include <cstdint>

#define BATCH 2
#define SEQ 2048
#define DMODEL 2048
#define NHEAD 16
#define HDIM 128
#define MTOT (BATCH*SEQ)   // 4096

// Scratch buffers (device globals: allocation-free)
__device__ float g_q[MTOT*DMODEL];
__device__ float g_k[MTOT*DMODEL];
__device__ float g_v[MTOT*DMODEL];
__device__ float g_ctx[MTOT*DMODEL];

// ---------------------------------------------------------------------------
// bf16x3 split-precision tensor-core GEMM:
// C[M,N] = A[M,K] @ B[N,K]^T (+ bias[N])
// Each fp32 value v is split v = hi + lo (both bf16); product computed as
// hi*hi + hi*lo + lo*hi via mma.sync.m16n8k16.bf16 with fp32 accumulate.
// Error ~2^-18 per product => rel_err ~4e-6 (threshold 1e-3).
// BM=BN=128, BK=32, 256 threads, warp tile 64x32, double-buffered smem.
// ---------------------------------------------------------------------------
#define GBM 128
#define GBN 128
#define GBK 32
#define APITCH 40            // halves per row (bank-conflict-free: row*20+t words)
#define TILE_HALVES (128*APITCH)

__device__ __forceinline__ void mma_bf16(float* c, const uint32_t* a, const uint32_t* b)
{
    asm volatile(
        "mma.sync.aligned.m16n8k16.row.col.f32.bf16.bf16.f32 "
        "{%0,%1,%2,%3}, {%4,%5,%6,%7}, {%8,%9}, {%0,%1,%2,%3};\n"
        : "+f"(c[0]), "+f"(c[1]), "+f"(c[2]), "+f"(c[3])
        : "r"(a[0]), "r"(a[1]), "r"(a[2]), "r"(a[3]), "r"(b[0]), "r"(b[1]));
}

__device__ __forceinline__ void cvt_store_row(__nv_bfloat16* Hh, __nv_bfloat16* Hl,
                                              int row, int c4, float4 v)
{
    __nv_bfloat16 h0 = __float2bfloat16(v.x);
    __nv_bfloat16 h1 = __float2bfloat16(v.y);
    __nv_bfloat16 h2 = __float2bfloat16(v.z);
    __nv_bfloat16 h3 = __float2bfloat16(v.w);
    __nv_bfloat16 l0 = __float2bfloat16(v.x - __bfloat162float(h0));
    __nv_bfloat16 l1 = __float2bfloat16(v.y - __bfloat162float(h1));
    __nv_bfloat16 l2 = __float2bfloat16(v.z - __bfloat162float(h2));
    __nv_bfloat16 l3 = __float2bfloat16(v.w - __bfloat162float(h3));
    __nv_bfloat162* ph = (__nv_bfloat162*)(Hh + row*APITCH + c4*4);
    ph[0] = __halves2bfloat162(h0, h1);
    ph[1] = __halves2bfloat162(h2, h3);
    __nv_bfloat162* pl = (__nv_bfloat162*)(Hl + row*APITCH + c4*4);
    pl[0] = __halves2bfloat162(l0, l1);
    pl[1] = __halves2bfloat162(l2, l3);
}

__global__ __launch_bounds__(256, 1)
void gemm_bf16x3(const float* __restrict__ A, const float* __restrict__ B,
                 float* __restrict__ C, const float* __restrict__ bias,
                 int M, int N, int K)
{
    extern __shared__ __nv_bfloat16 smem[];
    __nv_bfloat16* Ah = smem;                      // [2][TILE_HALVES]
    __nv_bfloat16* Al = smem + 2*TILE_HALVES;
    __nv_bfloat16* Bh = smem + 4*TILE_HALVES;
    __nv_bfloat16* Bl = smem + 6*TILE_HALVES;

    const int tid  = threadIdx.x;
    const int lane = tid & 31;
    const int wid  = tid >> 5;
    const int wm   = wid & 1;     // warp m: 0..1 (64 rows each)
    const int wn   = wid >> 1;    // warp n: 0..3 (32 cols each)
    const int g    = lane >> 2;   // group 0..7
    const int t    = lane & 3;    // thread-in-group

    const int m0 = blockIdx.y * GBM;
    const int n0 = blockIdx.x * GBN;

    const float* Abase = A + (long)m0 * K;
    const float* Bbase = B + (long)n0 * K;

    // gmem load mapping: float4 index f = tid + 256*i, row = f>>3, c4 = f&7
    const int lrow = tid >> 3;        // base row for i=0 (rows advance by 32 per i)
    const int lc4  = tid & 7;

    float acc[4][4][4];
#pragma unroll
    for (int mf = 0; mf < 4; mf++)
#pragma unroll
        for (int nf = 0; nf < 4; nf++)
#pragma unroll
            for (int c = 0; c < 4; c++) acc[mf][nf][c] = 0.f;

    // prologue: load + convert stage 0
#pragma unroll
    for (int i = 0; i < 4; i++) {
        int row = lrow + 32*i;
        float4 va = *(const float4*)(Abase + (long)row*K + lc4*4);
        float4 vb = *(const float4*)(Bbase + (long)row*K + lc4*4);
        cvt_store_row(Ah, Al, row, lc4, va);
        cvt_store_row(Bh, Bl, row, lc4, vb);
    }
    __syncthreads();

    const int nk = K / GBK;   // 64
    for (int kt = 0; kt < nk; kt++) {
        const int buf = kt & 1;
        const uint32_t* Ah32 = (const uint32_t*)(Ah + buf*TILE_HALVES);
        const uint32_t* Al32 = (const uint32_t*)(Al + buf*TILE_HALVES);
        const uint32_t* Bh32 = (const uint32_t*)(Bh + buf*TILE_HALVES);
        const uint32_t* Bl32 = (const uint32_t*)(Bl + buf*TILE_HALVES);

        // prefetch next k-tile from gmem
        float4 pa[4], pb[4];
        if (kt + 1 < nk) {
            const int kofs = (kt+1) * GBK;
#pragma unroll
            for (int i = 0; i < 4; i++) {
                int row = lrow + 32*i;
                pa[i] = *(const float4*)(Abase + (long)row*K + kofs + lc4*4);
                pb[i] = *(const float4*)(Bbase + (long)row*K + kofs + lc4*4);
            }
        }

#pragma unroll
        for (int ks = 0; ks < 2; ks++) {
            const int kw = ks*8 + t;     // word offset within row
            uint32_t ah[4][4], al[4][4], bh[4][2], bl[4][2];
#pragma unroll
            for (int mf = 0; mf < 4; mf++) {
                int r0 = (wm*64 + mf*16 + g) * (APITCH/2);
                int r1 = r0 + 8*(APITCH/2);
                ah[mf][0] = Ah32[r0 + kw];
                ah[mf][1] = Ah32[r1 + kw];
                ah[mf][2] = Ah32[r0 + kw + 4];
                ah[mf][3] = Ah32[r1 + kw + 4];
                al[mf][0] = Al32[r0 + kw];
                al[mf][1] = Al32[r1 + kw];
                al[mf][2] = Al32[r0 + kw + 4];
                al[mf][3] = Al32[r1 + kw + 4];
            }
#pragma unroll
            for (int nf = 0; nf < 4; nf++) {
                int rb = (wn*32 + nf*8 + g) * (APITCH/2);
                bh[nf][0] = Bh32[rb + kw];
                bh[nf][1] = Bh32[rb + kw + 4];
                bl[nf][0] = Bl32[rb + kw];
                bl[nf][1] = Bl32[rb + kw + 4];
            }
            // hi*hi pass
#pragma unroll
            for (int mf = 0; mf < 4; mf++)
#pragma unroll
                for (int nf = 0; nf < 4; nf++)
                    mma_bf16(acc[mf][nf], ah[mf], bh[nf]);
            // hi*lo pass
#pragma unroll
            for (int mf = 0; mf < 4; mf++)
#pragma unroll
                for (int nf = 0; nf < 4; nf++)
                    mma_bf16(acc[mf][nf], ah[mf], bl[nf]);
            // lo*hi pass
#pragma unroll
            for (int mf = 0; mf < 4; mf++)
#pragma unroll
                for (int nf = 0; nf < 4; nf++)
                    mma_bf16(acc[mf][nf], al[mf], bh[nf]);
        }

        // store prefetched tile into the other buffer
        if (kt + 1 < nk) {
            const int nb = buf ^ 1;
#pragma unroll
            for (int i = 0; i < 4; i++) {
                int row = lrow + 32*i;
                cvt_store_row(Ah + nb*TILE_HALVES, Al + nb*TILE_HALVES, row, lc4, pa[i]);
                cvt_store_row(Bh + nb*TILE_HALVES, Bl + nb*TILE_HALVES, row, lc4, pb[i]);
            }
        }
        __syncthreads();
    }

    // epilogue
#pragma unroll
    for (int nf = 0; nf < 4; nf++) {
        int col = n0 + wn*32 + nf*8 + 2*t;
        float b0 = bias ? bias[col]     : 0.f;
        float b1 = bias ? bias[col + 1] : 0.f;
#pragma unroll
        for (int mf = 0; mf < 4; mf++) {
            int row = m0 + wm*64 + mf*16 + g;
            float2 r0 = make_float2(acc[mf][nf][0] + b0, acc[mf][nf][1] + b1);
            float2 r1 = make_float2(acc[mf][nf][2] + b0, acc[mf][nf][3] + b1);
            *(float2*)(C + (long)row*N + col)       = r0;
            *(float2*)(C + (long)(row+8)*N + col)   = r1;
        }
    }
}

// ---------------------------------------------------------------------------
// Causal flash attention, fp32 (unchanged from R2 — L1-bound, next target).
// ---------------------------------------------------------------------------
__global__ __launch_bounds__(256)
void attn_kernel(const float* __restrict__ Q, const float* __restrict__ K,
                 const float* __restrict__ V, float* __restrict__ O)
{
    extern __shared__ float sm[];
    float* Qt = sm;                 // [128][64]
    float* Kt = Qt + 128*64;        // [128][64]
    float* Vs = Kt + 128*64;        // [64][128]
    float* Ps = Vs + 64*128;        // [64][64]

    const int tid = threadIdx.x;
    const int ty  = tid >> 4;
    const int tx  = tid & 15;
    const int qt  = blockIdx.x;
    const int h   = blockIdx.y;
    const int b   = blockIdx.z;
    const int q0  = qt * 64;

    const float* Qg = Q + ((long)(b*SEQ + q0)) * DMODEL + h*HDIM;

#pragma unroll
    for (int i = 0; i < 8; i++) {
        int id = tid + 256 * i;
        int r  = id >> 5;
        int kc = (id & 31) * 4;
        float4 v4 = *(const float4*)(Qg + (long)r * DMODEL + kc);
        Qt[(kc+0)*64 + r] = v4.x;
        Qt[(kc+1)*64 + r] = v4.y;
        Qt[(kc+2)*64 + r] = v4.z;
        Qt[(kc+3)*64 + r] = v4.w;
    }

    float m[4], l[4], o[4][8];
#pragma unroll
    for (int i = 0; i < 4; i++) {
        m[i] = -1e30f; l[i] = 0.f;
#pragma unroll
        for (int c = 0; c < 8; c++) o[i][c] = 0.f;
    }

    const float sm_scale = 0.08838834764831845f;

    __syncthreads();

    for (int kt = 0; kt <= qt; kt++) {
        const int k0 = kt * 64;
        const float* Kg = K + ((long)(b*SEQ + k0)) * DMODEL + h*HDIM;
        const float* Vg = V + ((long)(b*SEQ + k0)) * DMODEL + h*HDIM;
#pragma unroll
        for (int i = 0; i < 8; i++) {
            int id = tid + 256 * i;
            int r  = id >> 5;
            int kc = (id & 31) * 4;
            float4 v4 = *(const float4*)(Kg + (long)r * DMODEL + kc);
            Kt[(kc+0)*64 + r] = v4.x;
            Kt[(kc+1)*64 + r] = v4.y;
            Kt[(kc+2)*64 + r] = v4.z;
            Kt[(kc+3)*64 + r] = v4.w;
            float4 w4 = *(const float4*)(Vg + (long)r * DMODEL + kc);
            *(float4*)&Vs[r*128 + kc] = w4;
        }
        __syncthreads();

        float s[4][4];
#pragma unroll
        for (int i = 0; i < 4; i++)
#pragma unroll
            for (int j = 0; j < 4; j++) s[i][j] = 0.f;

        for (int kk = 0; kk < 128; kk++) {
            float4 a  = *(const float4*)&Qt[kk*64 + ty*4];
            float4 bq = *(const float4*)&Kt[kk*64 + tx*4];
            float av[4] = {a.x, a.y, a.z, a.w};
            float bv[4] = {bq.x, bq.y, bq.z, bq.w};
#pragma unroll
            for (int i = 0; i < 4; i++)
#pragma unroll
                for (int j = 0; j < 4; j++) s[i][j] += av[i]*bv[j];
        }

#pragma unroll
        for (int i = 0; i < 4; i++) {
            int qg = q0 + ty*4 + i;
#pragma unroll
            for (int j = 0; j < 4; j++) {
                int kg = k0 + tx*4 + j;
                s[i][j] = (kg <= qg) ? s[i][j]*sm_scale : -1e30f;
            }
        }

#pragma unroll
        for (int i = 0; i < 4; i++) {
            float mx = fmaxf(fmaxf(s[i][0], s[i][1]), fmaxf(s[i][2], s[i][3]));
#pragma unroll
            for (int off = 8; off > 0; off >>= 1)
                mx = fmaxf(mx, __shfl_xor_sync(0xffffffffu, mx, off));
            float mnew = fmaxf(m[i], mx);
            float corr = __expf(m[i] - mnew);
            float p[4], rs = 0.f;
#pragma unroll
            for (int j = 0; j < 4; j++) { p[j] = __expf(s[i][j] - mnew); rs += p[j]; }
#pragma unroll
            for (int off = 8; off > 0; off >>= 1)
                rs += __shfl_xor_sync(0xffffffffu, rs, off);
            l[i] = l[i]*corr + rs;
            m[i] = mnew;
#pragma unroll
            for (int c = 0; c < 8; c++) o[i][c] *= corr;
            *(float4*)&Ps[(ty*4 + i)*64 + tx*4] = make_float4(p[0], p[1], p[2], p[3]);
        }
        __syncthreads();

#pragma unroll 4
        for (int j = 0; j < 64; j++) {
            float pr[4];
#pragma unroll
            for (int i = 0; i < 4; i++) pr[i] = Ps[(ty*4 + i)*64 + j];
            float4 v0 = *(const float4*)&Vs[j*128 + tx*8];
            float4 v1 = *(const float4*)&Vs[j*128 + tx*8 + 4];
            float vv[8] = {v0.x,v0.y,v0.z,v0.w,v1.x,v1.y,v1.z,v1.w};
#pragma unroll
            for (int i = 0; i < 4; i++)
#pragma unroll
                for (int c = 0; c < 8; c++) o[i][c] += pr[i]*vv[c];
        }
        __syncthreads();
    }

    float* Og = O + ((long)(b*SEQ + q0)) * DMODEL + h*HDIM;
#pragma unroll
    for (int i = 0; i < 4; i++) {
        float inv = 1.f / l[i];
        float4 r0 = make_float4(o[i][0]*inv, o[i][1]*inv, o[i][2]*inv, o[i][3]*inv);
        float4 r1 = make_float4(o[i][4]*inv, o[i][5]*inv, o[i][6]*inv, o[i][7]*inv);
        *(float4*)(Og + (long)(ty*4 + i)*DMODEL + tx*8)     = r0;
        *(float4*)(Og + (long)(ty*4 + i)*DMODEL + tx*8 + 4) = r1;
    }
}

// ---------------------------------------------------------------------------
// Host launcher
// ---------------------------------------------------------------------------
extern "C" void kernel_launch(void* const* d_in, const int* in_sizes, int n_in,
                              void* d_out, int out_size)
{
    const float* x  = (const float*)d_in[0];
    const float* wq = (const float*)d_in[1];
    const float* wk = (const float*)d_in[2];
    const float* wv = (const float*)d_in[3];
    const float* wo = (const float*)d_in[4];
    const float* bo = (const float*)d_in[5];
    float* out = (float*)d_out;

    float *q, *k, *v, *ctx;
    cudaGetSymbolAddress((void**)&q,   g_q);
    cudaGetSymbolAddress((void**)&k,   g_k);
    cudaGetSymbolAddress((void**)&v,   g_v);
    cudaGetSymbolAddress((void**)&ctx, g_ctx);

    const int GEMM_SMEM = 8 * TILE_HALVES * (int)sizeof(__nv_bfloat16); // 81920
    static bool configured = false;
    if (!configured) {
        cudaFuncSetAttribute(gemm_bf16x3, cudaFuncAttributeMaxDynamicSharedMemorySize, GEMM_SMEM);
        const int ATTN_SMEM = (128*64 + 128*64 + 64*128 + 64*64) * (int)sizeof(float);
        cudaFuncSetAttribute(attn_kernel, cudaFuncAttributeMaxDynamicSharedMemorySize, ATTN_SMEM);
        configured = true;
    }
    const int ATTN_SMEM = (128*64 + 128*64 + 64*128 + 64*64) * (int)sizeof(float); // 114688

    dim3 gg(DMODEL/GBN, MTOT/GBM);   // 16 x 32 = 512 CTAs per GEMM
    gemm_bf16x3<<<gg, 256, GEMM_SMEM>>>(x,   wq, q,   nullptr, MTOT, DMODEL, DMODEL);
    gemm_bf16x3<<<gg, 256, GEMM_SMEM>>>(x,   wk, k,   nullptr, MTOT, DMODEL, DMODEL);
    gemm_bf16x3<<<gg, 256, GEMM_SMEM>>>(x,   wv, v,   nullptr, MTOT, DMODEL, DMODEL);

    attn_kernel<<<dim3(SEQ/64, NHEAD, BATCH), 256, ATTN_SMEM>>>(q, k, v, ctx);

    gemm_bf16x3<<<gg, 256, GEMM_SMEM>>>(ctx, wo, out, bo, MTOT, DMODEL, DMODEL);
}

// round 4
// speedup vs baseline: 2.9496x; 1.6786x over previous
#include <cuda_runtime.h>
#include <cuda_bf16.h>
#include <cstdint>

#define BATCH 2
#define SEQ 2048
#define DMODEL 2048
#define NHEAD 16
#define HDIM 128
#define MTOT (BATCH*SEQ)          // 4096
#define NTOK (MTOT*DMODEL)        // 8388608
#define NW   (DMODEL*DMODEL)      // 4194304

// ---------------- scratch (device globals: allocation-free) ----------------
__device__ alignas(16) __nv_bfloat16 g_xs_h[NTOK], g_xs_l[NTOK];
__device__ alignas(16) __nv_bfloat16 g_wq_h[NW],  g_wq_l[NW];
__device__ alignas(16) __nv_bfloat16 g_wk_h[NW],  g_wk_l[NW];
__device__ alignas(16) __nv_bfloat16 g_wv_h[NW],  g_wv_l[NW];
__device__ alignas(16) __nv_bfloat16 g_wo_h[NW],  g_wo_l[NW];
__device__ alignas(16) __nv_bfloat16 g_q_h[NTOK], g_q_l[NTOK];
__device__ alignas(16) __nv_bfloat16 g_k_h[NTOK], g_k_l[NTOK];
__device__ alignas(16) __nv_bfloat16 g_v_h[NTOK], g_v_l[NTOK];
__device__ alignas(16) __nv_bfloat16 g_vt_h[NTOK], g_vt_l[NTOK];
__device__ alignas(16) __nv_bfloat16 g_c_h[NTOK], g_c_l[NTOK];

// ---------------- helpers ----------------
__device__ __forceinline__ void mma_bf16(float* c, const uint32_t* a, const uint32_t* b)
{
    asm volatile(
        "mma.sync.aligned.m16n8k16.row.col.f32.bf16.bf16.f32 "
        "{%0,%1,%2,%3}, {%4,%5,%6,%7}, {%8,%9}, {%0,%1,%2,%3};\n"
        : "+f"(c[0]), "+f"(c[1]), "+f"(c[2]), "+f"(c[3])
        : "r"(a[0]), "r"(a[1]), "r"(a[2]), "r"(a[3]), "r"(b[0]), "r"(b[1]));
}

__device__ __forceinline__ uint32_t pack_split(float x, float y, uint32_t& lo_out)
{
    __nv_bfloat16 hx = __float2bfloat16(x);
    __nv_bfloat16 hy = __float2bfloat16(y);
    __nv_bfloat16 lx = __float2bfloat16(x - __bfloat162float(hx));
    __nv_bfloat16 ly = __float2bfloat16(y - __bfloat162float(hy));
    __nv_bfloat162 h2 = __halves2bfloat162(hx, hy);
    __nv_bfloat162 l2 = __halves2bfloat162(lx, ly);
    lo_out = *(uint32_t*)&l2;
    return *(uint32_t*)&h2;
}

// ---------------- fp32 -> bf16 hi/lo split ----------------
__global__ void split_kernel(const float4* __restrict__ src,
                             uint2* __restrict__ hi, uint2* __restrict__ lo, int n4)
{
    int i = blockIdx.x * blockDim.x + threadIdx.x;
    if (i >= n4) return;
    float4 v = src[i];
    uint32_t l0, l1;
    uint32_t h0 = pack_split(v.x, v.y, l0);
    uint32_t h1 = pack_split(v.z, v.w, l1);
    hi[i] = make_uint2(h0, h1);
    lo[i] = make_uint2(l0, l1);
}

// ---------------- per-batch 2048x2048 bf16 transpose ----------------
__global__ void transpose_bf16(const __nv_bfloat16* __restrict__ in,
                               __nv_bfloat16* __restrict__ out)
{
    __shared__ __nv_bfloat16 tile[32][33];
    const int bx = blockIdx.x * 32;   // hd base
    const int by = blockIdx.y * 32;   // s base
    const long boff = (long)blockIdx.z * 2048 * 2048;
    const int tx = threadIdx.x & 31;
    const int ty = threadIdx.x >> 5;  // 0..7
#pragma unroll
    for (int j = 0; j < 4; j++) {
        int sl = ty + j*8;
        tile[sl][tx] = in[boff + (long)(by + sl)*2048 + bx + tx];
    }
    __syncthreads();
#pragma unroll
    for (int j = 0; j < 4; j++) {
        int hl = ty + j*8;
        out[boff + (long)(bx + hl)*2048 + by + tx] = tile[tx][hl];
    }
}

// ---------------------------------------------------------------------------
// bf16x3 tensor-core GEMM on pre-split operands.
// C[M,N] = (Ah+Al)[M,K] @ (Bh+Bl)[N,K]^T  via hh + hl + lh passes.
// SPLIT_OUT: write C as bf16 hi/lo pair; else fp32 (+bias).
// ---------------------------------------------------------------------------
#define GBM 128
#define GBN 128
#define GBK 32
#define APITCH 40
#define TILE_H (128*APITCH)

template<bool SPLIT_OUT>
__global__ __launch_bounds__(256, 1)
void gemm_pre(const __nv_bfloat16* __restrict__ Agh, const __nv_bfloat16* __restrict__ Agl,
              const __nv_bfloat16* __restrict__ Bgh, const __nv_bfloat16* __restrict__ Bgl,
              float* __restrict__ Cf,
              __nv_bfloat16* __restrict__ Ch, __nv_bfloat16* __restrict__ Cl,
              const float* __restrict__ bias, int M, int N, int K)
{
    extern __shared__ __nv_bfloat16 smem[];
    __nv_bfloat16* sAh = smem;                 // [2][TILE_H]
    __nv_bfloat16* sAl = smem + 2*TILE_H;
    __nv_bfloat16* sBh = smem + 4*TILE_H;
    __nv_bfloat16* sBl = smem + 6*TILE_H;

    const int tid  = threadIdx.x;
    const int lane = tid & 31;
    const int wid  = tid >> 5;
    const int wm   = wid & 1;
    const int wn   = wid >> 1;
    const int g    = lane >> 2;
    const int t    = lane & 3;

    const int m0 = blockIdx.y * GBM;
    const int n0 = blockIdx.x * GBN;

    const int lr = tid >> 2;            // 0..63: tile row / 2 regions handled by i
    const int lc = (tid & 3) * 8;       // half offset within 32

    float acc[4][4][4];
#pragma unroll
    for (int mf = 0; mf < 4; mf++)
#pragma unroll
        for (int nf = 0; nf < 4; nf++)
#pragma unroll
            for (int c = 0; c < 4; c++) acc[mf][nf][c] = 0.f;

    // prologue: tile 0 (each thread: 2 uint4 per array, rows lr and lr+64)
#pragma unroll
    for (int i = 0; i < 2; i++) {
        int r = lr + 64*i;
        *(uint4*)(sAh + r*APITCH + lc) = *(const uint4*)(Agh + (long)(m0+r)*K + lc);
        *(uint4*)(sAl + r*APITCH + lc) = *(const uint4*)(Agl + (long)(m0+r)*K + lc);
        *(uint4*)(sBh + r*APITCH + lc) = *(const uint4*)(Bgh + (long)(n0+r)*K + lc);
        *(uint4*)(sBl + r*APITCH + lc) = *(const uint4*)(Bgl + (long)(n0+r)*K + lc);
    }
    __syncthreads();

    const int nk = K / GBK;
    for (int kt = 0; kt < nk; kt++) {
        const int buf = kt & 1;
        const uint32_t* Ah32 = (const uint32_t*)(sAh + buf*TILE_H);
        const uint32_t* Al32 = (const uint32_t*)(sAl + buf*TILE_H);
        const uint32_t* Bh32 = (const uint32_t*)(sBh + buf*TILE_H);
        const uint32_t* Bl32 = (const uint32_t*)(sBl + buf*TILE_H);

        uint4 pah[2], pal[2], pbh[2], pbl[2];
        if (kt + 1 < nk) {
            const int ko = (kt+1)*GBK + lc;
#pragma unroll
            for (int i = 0; i < 2; i++) {
                int r = lr + 64*i;
                pah[i] = *(const uint4*)(Agh + (long)(m0+r)*K + ko);
                pal[i] = *(const uint4*)(Agl + (long)(m0+r)*K + ko);
                pbh[i] = *(const uint4*)(Bgh + (long)(n0+r)*K + ko);
                pbl[i] = *(const uint4*)(Bgl + (long)(n0+r)*K + ko);
            }
        }

#pragma unroll
        for (int ks = 0; ks < 2; ks++) {
            const int kw = ks*8 + t;
            uint32_t ah[4][4], al[4][4], bh[4][2], bl[4][2];
#pragma unroll
            for (int mf = 0; mf < 4; mf++) {
                int r0 = (wm*64 + mf*16 + g) * (APITCH/2);
                int r1 = r0 + 8*(APITCH/2);
                ah[mf][0] = Ah32[r0 + kw];  ah[mf][1] = Ah32[r1 + kw];
                ah[mf][2] = Ah32[r0 + kw + 4]; ah[mf][3] = Ah32[r1 + kw + 4];
                al[mf][0] = Al32[r0 + kw];  al[mf][1] = Al32[r1 + kw];
                al[mf][2] = Al32[r0 + kw + 4]; al[mf][3] = Al32[r1 + kw + 4];
            }
#pragma unroll
            for (int nf = 0; nf < 4; nf++) {
                int rb = (wn*32 + nf*8 + g) * (APITCH/2);
                bh[nf][0] = Bh32[rb + kw];  bh[nf][1] = Bh32[rb + kw + 4];
                bl[nf][0] = Bl32[rb + kw];  bl[nf][1] = Bl32[rb + kw + 4];
            }
#pragma unroll
            for (int mf = 0; mf < 4; mf++)
#pragma unroll
                for (int nf = 0; nf < 4; nf++)
                    mma_bf16(acc[mf][nf], ah[mf], bh[nf]);
#pragma unroll
            for (int mf = 0; mf < 4; mf++)
#pragma unroll
                for (int nf = 0; nf < 4; nf++)
                    mma_bf16(acc[mf][nf], ah[mf], bl[nf]);
#pragma unroll
            for (int mf = 0; mf < 4; mf++)
#pragma unroll
                for (int nf = 0; nf < 4; nf++)
                    mma_bf16(acc[mf][nf], al[mf], bh[nf]);
        }

        if (kt + 1 < nk) {
            const int nb = buf ^ 1;
#pragma unroll
            for (int i = 0; i < 2; i++) {
                int r = lr + 64*i;
                *(uint4*)(sAh + nb*TILE_H + r*APITCH + lc) = pah[i];
                *(uint4*)(sAl + nb*TILE_H + r*APITCH + lc) = pal[i];
                *(uint4*)(sBh + nb*TILE_H + r*APITCH + lc) = pbh[i];
                *(uint4*)(sBl + nb*TILE_H + r*APITCH + lc) = pbl[i];
            }
        }
        __syncthreads();
    }

    // epilogue
#pragma unroll
    for (int nf = 0; nf < 4; nf++) {
        int col = n0 + wn*32 + nf*8 + 2*t;
        float b0 = 0.f, b1 = 0.f;
        if (!SPLIT_OUT && bias) { b0 = bias[col]; b1 = bias[col + 1]; }
#pragma unroll
        for (int mf = 0; mf < 4; mf++) {
            int row = m0 + wm*64 + mf*16 + g;
            if (SPLIT_OUT) {
                uint32_t l0, l1;
                uint32_t h0 = pack_split(acc[mf][nf][0], acc[mf][nf][1], l0);
                uint32_t h1 = pack_split(acc[mf][nf][2], acc[mf][nf][3], l1);
                *(uint32_t*)(Ch + (long)row*N + col)     = h0;
                *(uint32_t*)(Cl + (long)row*N + col)     = l0;
                *(uint32_t*)(Ch + (long)(row+8)*N + col) = h1;
                *(uint32_t*)(Cl + (long)(row+8)*N + col) = l1;
            } else {
                *(float2*)(Cf + (long)row*N + col)     = make_float2(acc[mf][nf][0]+b0, acc[mf][nf][1]+b1);
                *(float2*)(Cf + (long)(row+8)*N + col) = make_float2(acc[mf][nf][2]+b0, acc[mf][nf][3]+b1);
            }
        }
    }
}

// ---------------------------------------------------------------------------
// Tensor-core causal flash attention, bf16x3 for QK^T and PV.
// CTA = 128 threads (4 warps), 64 queries; warp owns 16 query rows.
// smem: Q hi/lo [64][136], K hi/lo [64][136], Vt hi/lo [128][72].
// ---------------------------------------------------------------------------
#define AP 136   // Q/K pitch in halves (68 words: 4g bank spread)
#define VP 72    // Vt pitch in halves (36 words)
#define ATTN_SMEM ((4*64*AP + 2*128*VP)*2)   // 106496 bytes

__global__ __launch_bounds__(128)
void attn_mma(const __nv_bfloat16* __restrict__ Qh, const __nv_bfloat16* __restrict__ Ql,
              const __nv_bfloat16* __restrict__ Kh, const __nv_bfloat16* __restrict__ Kl,
              const __nv_bfloat16* __restrict__ Vth, const __nv_bfloat16* __restrict__ Vtl,
              __nv_bfloat16* __restrict__ Ch, __nv_bfloat16* __restrict__ Cl)
{
    extern __shared__ __nv_bfloat16 sm[];
    __nv_bfloat16* sQh = sm;
    __nv_bfloat16* sQl = sQh + 64*AP;
    __nv_bfloat16* sKh = sQl + 64*AP;
    __nv_bfloat16* sKl = sKh + 64*AP;
    __nv_bfloat16* sVh = sKl + 64*AP;   // Vt: [128 d][VP]
    __nv_bfloat16* sVl = sVh + 128*VP;

    const int tid  = threadIdx.x;
    const int lane = tid & 31;
    const int wid  = tid >> 5;          // 0..3
    const int g    = lane >> 2;
    const int t    = lane & 3;

    const int qt = blockIdx.x;
    const int h  = blockIdx.y;
    const int b  = blockIdx.z;
    const int q0 = qt * 64;

    // ---- load Q tile (hi/lo), 8 uint4 each per thread ----
    const long qbase = ((long)(b*SEQ + q0))*DMODEL + h*HDIM;
#pragma unroll
    for (int i = 0; i < 8; i++) {
        int u = tid + 128*i;
        int r = u >> 4, c = (u & 15)*8;
        *(uint4*)(sQh + r*AP + c) = *(const uint4*)(Qh + qbase + (long)r*DMODEL + c);
        *(uint4*)(sQl + r*AP + c) = *(const uint4*)(Ql + qbase + (long)r*DMODEL + c);
    }

    float accO[16][4];
#pragma unroll
    for (int nb = 0; nb < 16; nb++)
#pragma unroll
        for (int c = 0; c < 4; c++) accO[nb][c] = 0.f;
    float m2[2] = {-1e30f, -1e30f};
    float lsum[2] = {0.f, 0.f};

    const float SC2 = 0.08838834764831845f * 1.4426950408889634f;  // scale*log2(e)
    const long vtbase = ((long)((b*NHEAD + h)*HDIM))*SEQ;           // Vt rows = dims

    for (int kt = 0; kt <= qt; kt++) {
        const int k0 = kt * 64;
        const long kbase = ((long)(b*SEQ + k0))*DMODEL + h*HDIM;
        // K tile
#pragma unroll
        for (int i = 0; i < 8; i++) {
            int u = tid + 128*i;
            int r = u >> 4, c = (u & 15)*8;
            *(uint4*)(sKh + r*AP + c) = *(const uint4*)(Kh + kbase + (long)r*DMODEL + c);
            *(uint4*)(sKl + r*AP + c) = *(const uint4*)(Kl + kbase + (long)r*DMODEL + c);
        }
        // Vt tile: rows = 128 dims, 64 keys wide
#pragma unroll
        for (int i = 0; i < 8; i++) {
            int u = tid + 128*i;
            int d = u >> 3, c = (u & 7)*8;
            *(uint4*)(sVh + d*VP + c) = *(const uint4*)(Vth + vtbase + (long)d*SEQ + k0 + c);
            *(uint4*)(sVl + d*VP + c) = *(const uint4*)(Vtl + vtbase + (long)d*SEQ + k0 + c);
        }
        __syncthreads();

        // ---- S = Q @ K^T (bf16x3) ----
        float s[8][4];
#pragma unroll
        for (int nb = 0; nb < 8; nb++)
#pragma unroll
            for (int c = 0; c < 4; c++) s[nb][c] = 0.f;

        const uint32_t* Qh32 = (const uint32_t*)sQh;
        const uint32_t* Ql32 = (const uint32_t*)sQl;
        const uint32_t* Kh32 = (const uint32_t*)sKh;
        const uint32_t* Kl32 = (const uint32_t*)sKl;
        const int rq = wid*16 + g;
#pragma unroll
        for (int kc = 0; kc < 8; kc++) {
            int w0 = rq*(AP/2) + kc*8 + t;
            int w1 = w0 + 8*(AP/2);
            uint32_t ah[4] = {Qh32[w0], Qh32[w1], Qh32[w0+4], Qh32[w1+4]};
            uint32_t al[4] = {Ql32[w0], Ql32[w1], Ql32[w0+4], Ql32[w1+4]};
#pragma unroll
            for (int nb = 0; nb < 8; nb++) {
                int wb = (nb*8 + g)*(AP/2) + kc*8 + t;
                uint32_t bh[2] = {Kh32[wb], Kh32[wb+4]};
                uint32_t bl[2] = {Kl32[wb], Kl32[wb+4]};
                mma_bf16(s[nb], ah, bh);
                mma_bf16(s[nb], ah, bl);
                mma_bf16(s[nb], al, bh);
            }
        }

        // causal mask on diagonal tile
        if (kt == qt) {
            const int r0 = wid*16 + g, r1 = r0 + 8;
#pragma unroll
            for (int nb = 0; nb < 8; nb++) {
                int c0 = nb*8 + 2*t, c1 = c0 + 1;
                if (c0 > r0) s[nb][0] = -1e30f;
                if (c1 > r0) s[nb][1] = -1e30f;
                if (c0 > r1) s[nb][2] = -1e30f;
                if (c1 > r1) s[nb][3] = -1e30f;
            }
        }

        // ---- online softmax (rows g and g+8; reduce across 4 t-lanes) ----
        float mx0 = -1e30f, mx1 = -1e30f;
#pragma unroll
        for (int nb = 0; nb < 8; nb++) {
            mx0 = fmaxf(mx0, fmaxf(s[nb][0], s[nb][1]));
            mx1 = fmaxf(mx1, fmaxf(s[nb][2], s[nb][3]));
        }
        mx0 *= SC2; mx1 *= SC2;
#pragma unroll
        for (int off = 1; off <= 2; off <<= 1) {
            mx0 = fmaxf(mx0, __shfl_xor_sync(0xffffffffu, mx0, off));
            mx1 = fmaxf(mx1, __shfl_xor_sync(0xffffffffu, mx1, off));
        }
        float mn0 = fmaxf(m2[0], mx0), mn1 = fmaxf(m2[1], mx1);
        float corr0 = exp2f(m2[0] - mn0), corr1 = exp2f(m2[1] - mn1);
        float sum0 = 0.f, sum1 = 0.f;
#pragma unroll
        for (int nb = 0; nb < 8; nb++) {
            s[nb][0] = exp2f(s[nb][0]*SC2 - mn0);
            s[nb][1] = exp2f(s[nb][1]*SC2 - mn0);
            s[nb][2] = exp2f(s[nb][2]*SC2 - mn1);
            s[nb][3] = exp2f(s[nb][3]*SC2 - mn1);
            sum0 += s[nb][0] + s[nb][1];
            sum1 += s[nb][2] + s[nb][3];
        }
#pragma unroll
        for (int off = 1; off <= 2; off <<= 1) {
            sum0 += __shfl_xor_sync(0xffffffffu, sum0, off);
            sum1 += __shfl_xor_sync(0xffffffffu, sum1, off);
        }
        lsum[0] = lsum[0]*corr0 + sum0;
        lsum[1] = lsum[1]*corr1 + sum1;
        m2[0] = mn0; m2[1] = mn1;
#pragma unroll
        for (int nb = 0; nb < 16; nb++) {
            accO[nb][0] *= corr0; accO[nb][1] *= corr0;
            accO[nb][2] *= corr1; accO[nb][3] *= corr1;
        }

        // ---- build P fragments (register-only; C-frag layout == A-frag layout) ----
        uint32_t pah[4][4], pal[4][4];
#pragma unroll
        for (int kc = 0; kc < 4; kc++) {
            pah[kc][0] = pack_split(s[2*kc][0],   s[2*kc][1],   pal[kc][0]);
            pah[kc][1] = pack_split(s[2*kc][2],   s[2*kc][3],   pal[kc][1]);
            pah[kc][2] = pack_split(s[2*kc+1][0], s[2*kc+1][1], pal[kc][2]);
            pah[kc][3] = pack_split(s[2*kc+1][2], s[2*kc+1][3], pal[kc][3]);
        }

        // ---- O += P @ V (bf16x3) ----
        const uint32_t* Vh32 = (const uint32_t*)sVh;
        const uint32_t* Vl32 = (const uint32_t*)sVl;
#pragma unroll
        for (int kc = 0; kc < 4; kc++) {
#pragma unroll
            for (int nb = 0; nb < 16; nb++) {
                int wb = (nb*8 + g)*(VP/2) + kc*8 + t;
                uint32_t bh[2] = {Vh32[wb], Vh32[wb+4]};
                uint32_t bl[2] = {Vl32[wb], Vl32[wb+4]};
                mma_bf16(accO[nb], pah[kc], bh);
                mma_bf16(accO[nb], pah[kc], bl);
                mma_bf16(accO[nb], pal[kc], bh);
            }
        }
        __syncthreads();
    }

    // ---- epilogue: normalize and write ctx split hi/lo ----
    const float inv0 = 1.f / lsum[0], inv1 = 1.f / lsum[1];
    const long obase = ((long)(b*SEQ + q0 + wid*16))*DMODEL + h*HDIM;
#pragma unroll
    for (int nb = 0; nb < 16; nb++) {
        int col = nb*8 + 2*t;
        uint32_t l0, l1;
        uint32_t h0 = pack_split(accO[nb][0]*inv0, accO[nb][1]*inv0, l0);
        uint32_t h1 = pack_split(accO[nb][2]*inv1, accO[nb][3]*inv1, l1);
        *(uint32_t*)(Ch + obase + (long)g*DMODEL + col)     = h0;
        *(uint32_t*)(Cl + obase + (long)g*DMODEL + col)     = l0;
        *(uint32_t*)(Ch + obase + (long)(g+8)*DMODEL + col) = h1;
        *(uint32_t*)(Cl + obase + (long)(g+8)*DMODEL + col) = l1;
    }
}

// ---------------------------------------------------------------------------
// Host launcher
// ---------------------------------------------------------------------------
extern "C" void kernel_launch(void* const* d_in, const int* in_sizes, int n_in,
                              void* d_out, int out_size)
{
    const float* x  = (const float*)d_in[0];
    const float* wq = (const float*)d_in[1];
    const float* wk = (const float*)d_in[2];
    const float* wv = (const float*)d_in[3];
    const float* wo = (const float*)d_in[4];
    const float* bo = (const float*)d_in[5];
    float* out = (float*)d_out;

    __nv_bfloat16 *xs_h, *xs_l, *wqh, *wql, *wkh, *wkl, *wvh, *wvl, *woh, *wol;
    __nv_bfloat16 *qh, *ql, *kh, *kl, *vh, *vl, *vth, *vtl, *ch, *cl;
    cudaGetSymbolAddress((void**)&xs_h, g_xs_h); cudaGetSymbolAddress((void**)&xs_l, g_xs_l);
    cudaGetSymbolAddress((void**)&wqh, g_wq_h);  cudaGetSymbolAddress((void**)&wql, g_wq_l);
    cudaGetSymbolAddress((void**)&wkh, g_wk_h);  cudaGetSymbolAddress((void**)&wkl, g_wk_l);
    cudaGetSymbolAddress((void**)&wvh, g_wv_h);  cudaGetSymbolAddress((void**)&wvl, g_wv_l);
    cudaGetSymbolAddress((void**)&woh, g_wo_h);  cudaGetSymbolAddress((void**)&wol, g_wo_l);
    cudaGetSymbolAddress((void**)&qh, g_q_h);    cudaGetSymbolAddress((void**)&ql, g_q_l);
    cudaGetSymbolAddress((void**)&kh, g_k_h);    cudaGetSymbolAddress((void**)&kl, g_k_l);
    cudaGetSymbolAddress((void**)&vh, g_v_h);    cudaGetSymbolAddress((void**)&vl, g_v_l);
    cudaGetSymbolAddress((void**)&vth, g_vt_h);  cudaGetSymbolAddress((void**)&vtl, g_vt_l);
    cudaGetSymbolAddress((void**)&ch, g_c_h);    cudaGetSymbolAddress((void**)&cl, g_c_l);

    const int GEMM_SMEM = 8 * TILE_H * (int)sizeof(__nv_bfloat16);  // 81920
    static bool configured = false;
    if (!configured) {
        cudaFuncSetAttribute(gemm_pre<true>,  cudaFuncAttributeMaxDynamicSharedMemorySize, GEMM_SMEM);
        cudaFuncSetAttribute(gemm_pre<false>, cudaFuncAttributeMaxDynamicSharedMemorySize, GEMM_SMEM);
        cudaFuncSetAttribute(attn_mma, cudaFuncAttributeMaxDynamicSharedMemorySize, ATTN_SMEM);
        configured = true;
    }

    // 1) split inputs
    split_kernel<<<(NTOK/4 + 255)/256, 256>>>((const float4*)x,  (uint2*)xs_h, (uint2*)xs_l, NTOK/4);
    split_kernel<<<(NW/4 + 255)/256, 256>>>((const float4*)wq, (uint2*)wqh, (uint2*)wql, NW/4);
    split_kernel<<<(NW/4 + 255)/256, 256>>>((const float4*)wk, (uint2*)wkh, (uint2*)wkl, NW/4);
    split_kernel<<<(NW/4 + 255)/256, 256>>>((const float4*)wv, (uint2*)wvh, (uint2*)wvl, NW/4);
    split_kernel<<<(NW/4 + 255)/256, 256>>>((const float4*)wo, (uint2*)woh, (uint2*)wol, NW/4);

    // 2) QKV projections (split outputs)
    dim3 gg(DMODEL/GBN, MTOT/GBM);
    gemm_pre<true><<<gg, 256, GEMM_SMEM>>>(xs_h, xs_l, wqh, wql, nullptr, qh, ql, nullptr, MTOT, DMODEL, DMODEL);
    gemm_pre<true><<<gg, 256, GEMM_SMEM>>>(xs_h, xs_l, wkh, wkl, nullptr, kh, kl, nullptr, MTOT, DMODEL, DMODEL);
    gemm_pre<true><<<gg, 256, GEMM_SMEM>>>(xs_h, xs_l, wvh, wvl, nullptr, vh, vl, nullptr, MTOT, DMODEL, DMODEL);

    // 3) V transpose (per batch 2048x2048), hi and lo
    transpose_bf16<<<dim3(64, 64, BATCH), 256>>>(vh, vth);
    transpose_bf16<<<dim3(64, 64, BATCH), 256>>>(vl, vtl);

    // 4) attention
    attn_mma<<<dim3(SEQ/64, NHEAD, BATCH), 128, ATTN_SMEM>>>(qh, ql, kh, kl, vth, vtl, ch, cl);

    // 5) output projection (fp32 + bias)
    gemm_pre<false><<<gg, 256, GEMM_SMEM>>>(ch, cl, woh, wol, out, nullptr, nullptr, bo, MTOT, DMODEL, DMODEL);
}

// round 6
// speedup vs baseline: 2.9556x; 1.0020x over previous
#include <cuda_runtime.h>
#include <cuda_bf16.h>
#include <cstdint>

#define BATCH 2
#define SEQ 2048
#define DMODEL 2048
#define NHEAD 16
#define HDIM 128
#define MTOT (BATCH*SEQ)          // 4096
#define NTOK (MTOT*DMODEL)        // 8388608
#define NW   (DMODEL*DMODEL)      // 4194304

// ---------------- scratch (device globals: allocation-free) ----------------
__device__ alignas(16) __nv_bfloat16 g_xs_h[NTOK], g_xs_l[NTOK];
__device__ alignas(16) __nv_bfloat16 g_wq_h[NW],  g_wq_l[NW];
__device__ alignas(16) __nv_bfloat16 g_wk_h[NW],  g_wk_l[NW];
__device__ alignas(16) __nv_bfloat16 g_wv_h[NW],  g_wv_l[NW];
__device__ alignas(16) __nv_bfloat16 g_wo_h[NW],  g_wo_l[NW];
__device__ alignas(16) __nv_bfloat16 g_q_h[NTOK], g_q_l[NTOK];
__device__ alignas(16) __nv_bfloat16 g_k_h[NTOK], g_k_l[NTOK];
__device__ alignas(16) __nv_bfloat16 g_v_h[NTOK], g_v_l[NTOK];
__device__ alignas(16) __nv_bfloat16 g_vt_h[NTOK], g_vt_l[NTOK];
__device__ alignas(16) __nv_bfloat16 g_c_h[NTOK], g_c_l[NTOK];

// ---------------- helpers ----------------
__device__ __forceinline__ uint32_t smem_u32(const void* p) {
    uint32_t a;
    asm("{ .reg .u64 t; cvta.to.shared.u64 t, %1; cvt.u32.u64 %0, t; }" : "=r"(a) : "l"(p));
    return a;
}

__device__ __forceinline__ void mma_bf16(float* c, const uint32_t* a, const uint32_t* b)
{
    asm volatile(
        "mma.sync.aligned.m16n8k16.row.col.f32.bf16.bf16.f32 "
        "{%0,%1,%2,%3}, {%4,%5,%6,%7}, {%8,%9}, {%0,%1,%2,%3};\n"
        : "+f"(c[0]), "+f"(c[1]), "+f"(c[2]), "+f"(c[3])
        : "r"(a[0]), "r"(a[1]), "r"(a[2]), "r"(a[3]), "r"(b[0]), "r"(b[1]));
}

__device__ __forceinline__ uint32_t pack_split(float x, float y, uint32_t& lo_out)
{
    __nv_bfloat16 hx = __float2bfloat16(x);
    __nv_bfloat16 hy = __float2bfloat16(y);
    __nv_bfloat16 lx = __float2bfloat16(x - __bfloat162float(hx));
    __nv_bfloat16 ly = __float2bfloat16(y - __bfloat162float(hy));
    __nv_bfloat162 h2 = __halves2bfloat162(hx, hy);
    __nv_bfloat162 l2 = __halves2bfloat162(lx, ly);
    lo_out = *(uint32_t*)&l2;
    return *(uint32_t*)&h2;
}

// cp.async primitives
__device__ __forceinline__ void cp16(uint32_t dst, const void* src) {
    asm volatile("cp.async.cg.shared.global [%0], [%1], 16;" :: "r"(dst), "l"(src));
}
__device__ __forceinline__ void cp_commit() {
    asm volatile("cp.async.commit_group;" ::: "memory");
}
template<int N> __device__ __forceinline__ void cp_wait() {
    asm volatile("cp.async.wait_group %0;" :: "n"(N) : "memory");
}

// ---------------- fp32 -> bf16 hi/lo split ----------------
__global__ void split_kernel(const float4* __restrict__ src,
                             uint2* __restrict__ hi, uint2* __restrict__ lo, int n4)
{
    int i = blockIdx.x * blockDim.x + threadIdx.x;
    if (i >= n4) return;
    float4 v = src[i];
    uint32_t l0, l1;
    uint32_t h0 = pack_split(v.x, v.y, l0);
    uint32_t h1 = pack_split(v.z, v.w, l1);
    hi[i] = make_uint2(h0, h1);
    lo[i] = make_uint2(l0, l1);
}

// ---------------- per-batch 2048x2048 bf16 transpose ----------------
__global__ void transpose_bf16(const __nv_bfloat16* __restrict__ in,
                               __nv_bfloat16* __restrict__ out)
{
    __shared__ __nv_bfloat16 tile[32][33];
    const int bx = blockIdx.x * 32;
    const int by = blockIdx.y * 32;
    const long boff = (long)blockIdx.z * 2048 * 2048;
    const int tx = threadIdx.x & 31;
    const int ty = threadIdx.x >> 5;
#pragma unroll
    for (int j = 0; j < 4; j++) {
        int sl = ty + j*8;
        tile[sl][tx] = in[boff + (long)(by + sl)*2048 + bx + tx];
    }
    __syncthreads();
#pragma unroll
    for (int j = 0; j < 4; j++) {
        int hl = ty + j*8;
        out[boff + (long)(bx + hl)*2048 + by + tx] = tile[tx][hl];
    }
}

// ---------------------------------------------------------------------------
// bf16x3 tensor-core GEMM, 3-stage cp.async pipeline.
// C[M,N] = (Ah+Al)[M,K] @ (Bh+Bl)[N,K]^T  via hh + hl + lh mma passes.
// BM=BN=128, BK=32, 256 threads, warp tile 64x32.
// ---------------------------------------------------------------------------
#define GBM 128
#define GBN 128
#define GBK 32
#define APITCH 40
#define STAGE_H (128*APITCH)              // halves per array per stage
#define STAGE_BYTES (4*STAGE_H*2)         // Ah,Al,Bh,Bl : 40960
#define NSTAGE 3
#define GEMM_SMEM (NSTAGE*STAGE_BYTES)    // 122880

__device__ __forceinline__ void issue_tile(uint32_t sb,
    const __nv_bfloat16* __restrict__ Ah, const __nv_bfloat16* __restrict__ Al,
    const __nv_bfloat16* __restrict__ Bh, const __nv_bfloat16* __restrict__ Bl,
    int m0, int n0, int K, int kofs, int tid)
{
#pragma unroll
    for (int i = 0; i < 2; i++) {
        int idx = tid + 256*i;
        int r = idx >> 2, c = idx & 3;
        uint32_t so = sb + (r*APITCH + c*8)*2;
        long ga = (long)(m0 + r)*K + kofs + c*8;
        long gb = (long)(n0 + r)*K + kofs + c*8;
        cp16(so,                 Ah + ga);
        cp16(so + STAGE_H*2,     Al + ga);
        cp16(so + 2*STAGE_H*2,   Bh + gb);
        cp16(so + 3*STAGE_H*2,   Bl + gb);
    }
}

template<bool SPLIT_OUT>
__global__ __launch_bounds__(256, 1)
void gemm_cp(const __nv_bfloat16* __restrict__ Agh, const __nv_bfloat16* __restrict__ Agl,
             const __nv_bfloat16* __restrict__ Bgh, const __nv_bfloat16* __restrict__ Bgl,
             float* __restrict__ Cf,
             __nv_bfloat16* __restrict__ Ch, __nv_bfloat16* __restrict__ Cl,
             const float* __restrict__ bias, int M, int N, int K)
{
    extern __shared__ __align__(16) char gsm[];
    const uint32_t smb = smem_u32(gsm);

    const int tid  = threadIdx.x;
    const int lane = tid & 31;
    const int wid  = tid >> 5;
    const int wm   = wid & 1;
    const int wn   = wid >> 1;
    const int g    = lane >> 2;
    const int t    = lane & 3;

    const int m0 = blockIdx.y * GBM;
    const int n0 = blockIdx.x * GBN;

    float acc[4][4][4];
#pragma unroll
    for (int mf = 0; mf < 4; mf++)
#pragma unroll
        for (int nf = 0; nf < 4; nf++)
#pragma unroll
            for (int c = 0; c < 4; c++) acc[mf][nf][c] = 0.f;

    const int nk = K / GBK;   // 64

    // prologue: stages 0 and 1 in flight
    issue_tile(smb,               Agh, Agl, Bgh, Bgl, m0, n0, K, 0,   tid);
    cp_commit();
    issue_tile(smb + STAGE_BYTES, Agh, Agl, Bgh, Bgl, m0, n0, K, GBK, tid);
    cp_commit();

    for (int kt = 0; kt < nk; kt++) {
        cp_wait<1>();           // group kt complete (always-commit keeps ids aligned)
        __syncthreads();

        // issue stage kt+2 (buffer freed by mma of kt-1)
        if (kt + 2 < nk)
            issue_tile(smb + ((kt+2)%NSTAGE)*STAGE_BYTES,
                       Agh, Agl, Bgh, Bgl, m0, n0, K, (kt+2)*GBK, tid);
        cp_commit();            // commit unconditionally to keep group count aligned

        const char* sbase = gsm + (kt % NSTAGE)*STAGE_BYTES;
        const uint32_t* Ah32 = (const uint32_t*)(sbase);
        const uint32_t* Al32 = (const uint32_t*)(sbase + STAGE_H*2);
        const uint32_t* Bh32 = (const uint32_t*)(sbase + 2*STAGE_H*2);
        const uint32_t* Bl32 = (const uint32_t*)(sbase + 3*STAGE_H*2);

#pragma unroll
        for (int ks = 0; ks < 2; ks++) {
            const int kw = ks*8 + t;
            uint32_t ah[4][4], al[4][4], bh[4][2], bl[4][2];
#pragma unroll
            for (int mf = 0; mf < 4; mf++) {
                int r0 = (wm*64 + mf*16 + g) * (APITCH/2);
                int r1 = r0 + 8*(APITCH/2);
                ah[mf][0] = Ah32[r0 + kw];     ah[mf][1] = Ah32[r1 + kw];
                ah[mf][2] = Ah32[r0 + kw + 4]; ah[mf][3] = Ah32[r1 + kw + 4];
                al[mf][0] = Al32[r0 + kw];     al[mf][1] = Al32[r1 + kw];
                al[mf][2] = Al32[r0 + kw + 4]; al[mf][3] = Al32[r1 + kw + 4];
            }
#pragma unroll
            for (int nf = 0; nf < 4; nf++) {
                int rb = (wn*32 + nf*8 + g) * (APITCH/2);
                bh[nf][0] = Bh32[rb + kw];  bh[nf][1] = Bh32[rb + kw + 4];
                bl[nf][0] = Bl32[rb + kw];  bl[nf][1] = Bl32[rb + kw + 4];
            }
#pragma unroll
            for (int mf = 0; mf < 4; mf++)
#pragma unroll
                for (int nf = 0; nf < 4; nf++)
                    mma_bf16(acc[mf][nf], ah[mf], bh[nf]);
#pragma unroll
            for (int mf = 0; mf < 4; mf++)
#pragma unroll
                for (int nf = 0; nf < 4; nf++)
                    mma_bf16(acc[mf][nf], ah[mf], bl[nf]);
#pragma unroll
            for (int mf = 0; mf < 4; mf++)
#pragma unroll
                for (int nf = 0; nf < 4; nf++)
                    mma_bf16(acc[mf][nf], al[mf], bh[nf]);
        }
        __syncthreads();
    }

    // epilogue
#pragma unroll
    for (int nf = 0; nf < 4; nf++) {
        int col = n0 + wn*32 + nf*8 + 2*t;
        float b0 = 0.f, b1 = 0.f;
        if (!SPLIT_OUT && bias) { b0 = bias[col]; b1 = bias[col + 1]; }
#pragma unroll
        for (int mf = 0; mf < 4; mf++) {
            int row = m0 + wm*64 + mf*16 + g;
            if (SPLIT_OUT) {
                uint32_t l0, l1;
                uint32_t h0 = pack_split(acc[mf][nf][0], acc[mf][nf][1], l0);
                uint32_t h1 = pack_split(acc[mf][nf][2], acc[mf][nf][3], l1);
                *(uint32_t*)(Ch + (long)row*N + col)     = h0;
                *(uint32_t*)(Cl + (long)row*N + col)     = l0;
                *(uint32_t*)(Ch + (long)(row+8)*N + col) = h1;
                *(uint32_t*)(Cl + (long)(row+8)*N + col) = l1;
            } else {
                *(float2*)(Cf + (long)row*N + col)     = make_float2(acc[mf][nf][0]+b0, acc[mf][nf][1]+b1);
                *(float2*)(Cf + (long)(row+8)*N + col) = make_float2(acc[mf][nf][2]+b0, acc[mf][nf][3]+b1);
            }
        }
    }
}

// ---------------------------------------------------------------------------
// Tensor-core causal flash attention, bf16x3 (R4 design + LPT block order).
// ---------------------------------------------------------------------------
#define AP 136
#define VP 72
#define ATTN_SMEM ((4*64*AP + 2*128*VP)*2)   // 106496 bytes

__global__ __launch_bounds__(128)
void attn_mma(const __nv_bfloat16* __restrict__ Qh, const __nv_bfloat16* __restrict__ Ql,
              const __nv_bfloat16* __restrict__ Kh, const __nv_bfloat16* __restrict__ Kl,
              const __nv_bfloat16* __restrict__ Vth, const __nv_bfloat16* __restrict__ Vtl,
              __nv_bfloat16* __restrict__ Ch, __nv_bfloat16* __restrict__ Cl)
{
    extern __shared__ __nv_bfloat16 sm[];
    __nv_bfloat16* sQh = sm;
    __nv_bfloat16* sQl = sQh + 64*AP;
    __nv_bfloat16* sKh = sQl + 64*AP;
    __nv_bfloat16* sKl = sKh + 64*AP;
    __nv_bfloat16* sVh = sKl + 64*AP;
    __nv_bfloat16* sVl = sVh + 128*VP;

    const int tid  = threadIdx.x;
    const int lane = tid & 31;
    const int wid  = tid >> 5;
    const int g    = lane >> 2;
    const int t    = lane & 3;

    const int qt = gridDim.x - 1 - blockIdx.x;   // heavy tiles scheduled first (LPT)
    const int h  = blockIdx.y;
    const int b  = blockIdx.z;
    const int q0 = qt * 64;

    const long qbase = ((long)(b*SEQ + q0))*DMODEL + h*HDIM;
#pragma unroll
    for (int i = 0; i < 8; i++) {
        int u = tid + 128*i;
        int r = u >> 4, c = (u & 15)*8;
        *(uint4*)(sQh + r*AP + c) = *(const uint4*)(Qh + qbase + (long)r*DMODEL + c);
        *(uint4*)(sQl + r*AP + c) = *(const uint4*)(Ql + qbase + (long)r*DMODEL + c);
    }

    float accO[16][4];
#pragma unroll
    for (int nb = 0; nb < 16; nb++)
#pragma unroll
        for (int c = 0; c < 4; c++) accO[nb][c] = 0.f;
    float m2[2] = {-1e30f, -1e30f};
    float lsum[2] = {0.f, 0.f};

    const float SC2 = 0.08838834764831845f * 1.4426950408889634f;
    const long vtbase = ((long)((b*NHEAD + h)*HDIM))*SEQ;

    for (int kt = 0; kt <= qt; kt++) {
        const int k0 = kt * 64;
        const long kbase = ((long)(b*SEQ + k0))*DMODEL + h*HDIM;
#pragma unroll
        for (int i = 0; i < 8; i++) {
            int u = tid + 128*i;
            int r = u >> 4, c = (u & 15)*8;
            *(uint4*)(sKh + r*AP + c) = *(const uint4*)(Kh + kbase + (long)r*DMODEL + c);
            *(uint4*)(sKl + r*AP + c) = *(const uint4*)(Kl + kbase + (long)r*DMODEL + c);
        }
#pragma unroll
        for (int i = 0; i < 8; i++) {
            int u = tid + 128*i;
            int d = u >> 3, c = (u & 7)*8;
            *(uint4*)(sVh + d*VP + c) = *(const uint4*)(Vth + vtbase + (long)d*SEQ + k0 + c);
            *(uint4*)(sVl + d*VP + c) = *(const uint4*)(Vtl + vtbase + (long)d*SEQ + k0 + c);
        }
        __syncthreads();

        float s[8][4];
#pragma unroll
        for (int nb = 0; nb < 8; nb++)
#pragma unroll
            for (int c = 0; c < 4; c++) s[nb][c] = 0.f;

        const uint32_t* Qh32 = (const uint32_t*)sQh;
        const uint32_t* Ql32 = (const uint32_t*)sQl;
        const uint32_t* Kh32 = (const uint32_t*)sKh;
        const uint32_t* Kl32 = (const uint32_t*)sKl;
        const int rq = wid*16 + g;
#pragma unroll
        for (int kc = 0; kc < 8; kc++) {
            int w0 = rq*(AP/2) + kc*8 + t;
            int w1 = w0 + 8*(AP/2);
            uint32_t ah[4] = {Qh32[w0], Qh32[w1], Qh32[w0+4], Qh32[w1+4]};
            uint32_t al[4] = {Ql32[w0], Ql32[w1], Ql32[w0+4], Ql32[w1+4]};
#pragma unroll
            for (int nb = 0; nb < 8; nb++) {
                int wb = (nb*8 + g)*(AP/2) + kc*8 + t;
                uint32_t bh[2] = {Kh32[wb], Kh32[wb+4]};
                uint32_t bl[2] = {Kl32[wb], Kl32[wb+4]};
                mma_bf16(s[nb], ah, bh);
                mma_bf16(s[nb], ah, bl);
                mma_bf16(s[nb], al, bh);
            }
        }

        if (kt == qt) {
            const int r0 = wid*16 + g, r1 = r0 + 8;
#pragma unroll
            for (int nb = 0; nb < 8; nb++) {
                int c0 = nb*8 + 2*t, c1 = c0 + 1;
                if (c0 > r0) s[nb][0] = -1e30f;
                if (c1 > r0) s[nb][1] = -1e30f;
                if (c0 > r1) s[nb][2] = -1e30f;
                if (c1 > r1) s[nb][3] = -1e30f;
            }
        }

        float mx0 = -1e30f, mx1 = -1e30f;
#pragma unroll
        for (int nb = 0; nb < 8; nb++) {
            mx0 = fmaxf(mx0, fmaxf(s[nb][0], s[nb][1]));
            mx1 = fmaxf(mx1, fmaxf(s[nb][2], s[nb][3]));
        }
        mx0 *= SC2; mx1 *= SC2;
#pragma unroll
        for (int off = 1; off <= 2; off <<= 1) {
            mx0 = fmaxf(mx0, __shfl_xor_sync(0xffffffffu, mx0, off));
            mx1 = fmaxf(mx1, __shfl_xor_sync(0xffffffffu, mx1, off));
        }
        float mn0 = fmaxf(m2[0], mx0), mn1 = fmaxf(m2[1], mx1);
        float corr0 = exp2f(m2[0] - mn0), corr1 = exp2f(m2[1] - mn1);
        float sum0 = 0.f, sum1 = 0.f;
#pragma unroll
        for (int nb = 0; nb < 8; nb++) {
            s[nb][0] = exp2f(s[nb][0]*SC2 - mn0);
            s[nb][1] = exp2f(s[nb][1]*SC2 - mn0);
            s[nb][2] = exp2f(s[nb][2]*SC2 - mn1);
            s[nb][3] = exp2f(s[nb][3]*SC2 - mn1);
            sum0 += s[nb][0] + s[nb][1];
            sum1 += s[nb][2] + s[nb][3];
        }
#pragma unroll
        for (int off = 1; off <= 2; off <<= 1) {
            sum0 += __shfl_xor_sync(0xffffffffu, sum0, off);
            sum1 += __shfl_xor_sync(0xffffffffu, sum1, off);
        }
        lsum[0] = lsum[0]*corr0 + sum0;
        lsum[1] = lsum[1]*corr1 + sum1;
        m2[0] = mn0; m2[1] = mn1;
#pragma unroll
        for (int nb = 0; nb < 16; nb++) {
            accO[nb][0] *= corr0; accO[nb][1] *= corr0;
            accO[nb][2] *= corr1; accO[nb][3] *= corr1;
        }

        uint32_t pah[4][4], pal[4][4];
#pragma unroll
        for (int kc = 0; kc < 4; kc++) {
            pah[kc][0] = pack_split(s[2*kc][0],   s[2*kc][1],   pal[kc][0]);
            pah[kc][1] = pack_split(s[2*kc][2],   s[2*kc][3],   pal[kc][1]);
            pah[kc][2] = pack_split(s[2*kc+1][0], s[2*kc+1][1], pal[kc][2]);
            pah[kc][3] = pack_split(s[2*kc+1][2], s[2*kc+1][3], pal[kc][3]);
        }

        const uint32_t* Vh32 = (const uint32_t*)sVh;
        const uint32_t* Vl32 = (const uint32_t*)sVl;
#pragma unroll
        for (int kc = 0; kc < 4; kc++) {
#pragma unroll
            for (int nb = 0; nb < 16; nb++) {
                int wb = (nb*8 + g)*(VP/2) + kc*8 + t;
                uint32_t bh[2] = {Vh32[wb], Vh32[wb+4]};
                uint32_t bl[2] = {Vl32[wb], Vl32[wb+4]};
                mma_bf16(accO[nb], pah[kc], bh);
                mma_bf16(accO[nb], pah[kc], bl);
                mma_bf16(accO[nb], pal[kc], bh);
            }
        }
        __syncthreads();
    }

    const float inv0 = 1.f / lsum[0], inv1 = 1.f / lsum[1];
    const long obase = ((long)(b*SEQ + q0 + wid*16))*DMODEL + h*HDIM;
#pragma unroll
    for (int nb = 0; nb < 16; nb++) {
        int col = nb*8 + 2*t;
        uint32_t l0, l1;
        uint32_t h0 = pack_split(accO[nb][0]*inv0, accO[nb][1]*inv0, l0);
        uint32_t h1 = pack_split(accO[nb][2]*inv1, accO[nb][3]*inv1, l1);
        *(uint32_t*)(Ch + obase + (long)g*DMODEL + col)     = h0;
        *(uint32_t*)(Cl + obase + (long)g*DMODEL + col)     = l0;
        *(uint32_t*)(Ch + obase + (long)(g+8)*DMODEL + col) = h1;
        *(uint32_t*)(Cl + obase + (long)(g+8)*DMODEL + col) = l1;
    }
}

// ---------------------------------------------------------------------------
// Host launcher
// ---------------------------------------------------------------------------
extern "C" void kernel_launch(void* const* d_in, const int* in_sizes, int n_in,
                              void* d_out, int out_size)
{
    const float* x  = (const float*)d_in[0];
    const float* wq = (const float*)d_in[1];
    const float* wk = (const float*)d_in[2];
    const float* wv = (const float*)d_in[3];
    const float* wo = (const float*)d_in[4];
    const float* bo = (const float*)d_in[5];
    float* out = (float*)d_out;

    __nv_bfloat16 *xs_h, *xs_l, *wqh, *wql, *wkh, *wkl, *wvh, *wvl, *woh, *wol;
    __nv_bfloat16 *qh, *ql, *kh, *kl, *vh, *vl, *vth, *vtl, *ch, *cl;
    cudaGetSymbolAddress((void**)&xs_h, g_xs_h); cudaGetSymbolAddress((void**)&xs_l, g_xs_l);
    cudaGetSymbolAddress((void**)&wqh, g_wq_h);  cudaGetSymbolAddress((void**)&wql, g_wq_l);
    cudaGetSymbolAddress((void**)&wkh, g_wk_h);  cudaGetSymbolAddress((void**)&wkl, g_wk_l);
    cudaGetSymbolAddress((void**)&wvh, g_wv_h);  cudaGetSymbolAddress((void**)&wvl, g_wv_l);
    cudaGetSymbolAddress((void**)&woh, g_wo_h);  cudaGetSymbolAddress((void**)&wol, g_wo_l);
    cudaGetSymbolAddress((void**)&qh, g_q_h);    cudaGetSymbolAddress((void**)&ql, g_q_l);
    cudaGetSymbolAddress((void**)&kh, g_k_h);    cudaGetSymbolAddress((void**)&kl, g_k_l);
    cudaGetSymbolAddress((void**)&vh, g_v_h);    cudaGetSymbolAddress((void**)&vl, g_v_l);
    cudaGetSymbolAddress((void**)&vth, g_vt_h);  cudaGetSymbolAddress((void**)&vtl, g_vt_l);
    cudaGetSymbolAddress((void**)&ch, g_c_h);    cudaGetSymbolAddress((void**)&cl, g_c_l);

    static bool configured = false;
    if (!configured) {
        cudaFuncSetAttribute(gemm_cp<true>,  cudaFuncAttributeMaxDynamicSharedMemorySize, GEMM_SMEM);
        cudaFuncSetAttribute(gemm_cp<false>, cudaFuncAttributeMaxDynamicSharedMemorySize, GEMM_SMEM);
        cudaFuncSetAttribute(attn_mma, cudaFuncAttributeMaxDynamicSharedMemorySize, ATTN_SMEM);
        configured = true;
    }

    // 1) split inputs
    split_kernel<<<(NTOK/4 + 255)/256, 256>>>((const float4*)x,  (uint2*)xs_h, (uint2*)xs_l, NTOK/4);
    split_kernel<<<(NW/4 + 255)/256, 256>>>((const float4*)wq, (uint2*)wqh, (uint2*)wql, NW/4);
    split_kernel<<<(NW/4 + 255)/256, 256>>>((const float4*)wk, (uint2*)wkh, (uint2*)wkl, NW/4);
    split_kernel<<<(NW/4 + 255)/256, 256>>>((const float4*)wv, (uint2*)wvh, (uint2*)wvl, NW/4);
    split_kernel<<<(NW/4 + 255)/256, 256>>>((const float4*)wo, (uint2*)woh, (uint2*)wol, NW/4);

    // 2) QKV projections (split outputs)
    dim3 gg(DMODEL/GBN, MTOT/GBM);   // (16, 32)
    gemm_cp<true><<<gg, 256, GEMM_SMEM>>>(xs_h, xs_l, wqh, wql, nullptr, qh, ql, nullptr, MTOT, DMODEL, DMODEL);
    gemm_cp<true><<<gg, 256, GEMM_SMEM>>>(xs_h, xs_l, wkh, wkl, nullptr, kh, kl, nullptr, MTOT, DMODEL, DMODEL);
    gemm_cp<true><<<gg, 256, GEMM_SMEM>>>(xs_h, xs_l, wvh, wvl, nullptr, vh, vl, nullptr, MTOT, DMODEL, DMODEL);

    // 3) V transpose (per batch 2048x2048), hi and lo
    transpose_bf16<<<dim3(64, 64, BATCH), 256>>>(vh, vth);
    transpose_bf16<<<dim3(64, 64, BATCH), 256>>>(vl, vtl);

    // 4) attention
    attn_mma<<<dim3(SEQ/64, NHEAD, BATCH), 128, ATTN_SMEM>>>(qh, ql, kh, kl, vth, vtl, ch, cl);

    // 5) output projection (fp32 + bias)
    gemm_cp<false><<<gg, 256, GEMM_SMEM>>>(ch, cl, woh, wol, out, nullptr, nullptr, bo, MTOT, DMODEL, DMODEL);
}